// round 13
// baseline (speedup 1.0000x reference)
#include <cuda_runtime.h>
#include <cuda_bf16.h>
#include <math.h>
#include <stdint.h>

// ---------------------------------------------------------------------------
// Problem constants
// ---------------------------------------------------------------------------
#define BS 4
#define NN 256
#define DX 256
#define HH 8
#define DF 32
#define DFF 1024
#define ROWS (BS * NN)            // 1024
#define EPS 1e-5f
#define JSPLIT 8
#define JCHUNK (NN / JSPLIT)      // 32

// ---------------------------------------------------------------------------
// Device scratch (no allocations allowed)
// ---------------------------------------------------------------------------
__device__ float g_Q [ROWS * DX];
__device__ float g_K [ROWS * DX];
__device__ float g_V [ROWS * DX];
__device__ float g_T [ROWS * DX];
__device__ float g_X1[ROWS * DX];
__device__ float g_H [ROWS * DFF];
__device__ float g_P [8 * ROWS * DX];                  // split-K partials
__device__ float4 g_SA[JSPLIT * ROWS * (DX / 4) * 2];  // attn partials (s4, acc4)
__device__ float g_dummy;

// ---------------------------------------------------------------------------
// No-op filler (keeps ncu's sampled launch slot aligned with attn_part).
// ---------------------------------------------------------------------------
__global__ void noop_kernel() { if (threadIdx.x == 0) g_dummy = 1.0f; }

// ---------------------------------------------------------------------------
// Double-buffered SGEMM: BM=32, BN=64, BK=16, 128 threads, 4x4 micro-tile,
// ping-pong SMEM, 1 sync/iter. Small tile -> big grid -> latency hiding.
// mode 0: fused-N (blockIdx.x spans matrices; bias added here)
// mode 1: split-K (blockIdx.z = K-chunk; partial to C + z*M*N; bias deferred)
// ---------------------------------------------------------------------------
struct GArgs {
    const float* A;
    const float* B[3];
    const float* bias[3];
    float* C[3];
    int M, N, lda;
    int kPerZ;
    int relu, mode;
};

#define BM 32
#define BN 64
#define BKK 16

__global__ __launch_bounds__(128)
void sgemm_kernel(GArgs a)
{
    __shared__ __align__(16) float As[2][BKK][BM];
    __shared__ __align__(16) float Bs[2][BKK][BN];

    const int tid = threadIdx.x;

    const float* __restrict__ B;
    const float* bias;
    float* C;
    int kStart, bn;
    if (a.mode == 1) {
        B = a.B[0]; bias = nullptr;
        C = a.C[0] + (size_t)blockIdx.z * a.M * a.N;
        kStart = blockIdx.z * a.kPerZ;
        bn = blockIdx.x * BN;
    } else {
        const int tilesPerMat = a.N / BN;
        const int sel = blockIdx.x / tilesPerMat;
        B = a.B[sel]; bias = a.bias[sel]; C = a.C[sel];
        kStart = 0;
        bn = (blockIdx.x - sel * tilesPerMat) * BN;
    }
    const int bm = blockIdx.y * BM;

    const int colb = (tid & 15) * 4;
    const int rowb = (tid >> 4) * 4;
    const int am = tid >> 2;
    const int ak = (tid & 3) * 4;
    const int bkr = tid >> 3;
    const int bn8 = (tid & 7) * 8;

    const float* Aptr = a.A + (size_t)(bm + am) * a.lda + kStart + ak;
    const float* Bptr = B + (size_t)(kStart + bkr) * a.N + bn + bn8;

    float acc[4][4] = {};
    const int nIter = a.kPerZ / BKK;

    float4 av  = *(const float4*)(Aptr);
    float4 bv0 = *(const float4*)(Bptr);
    float4 bv1 = *(const float4*)(Bptr + 4);
    As[0][ak + 0][am] = av.x; As[0][ak + 1][am] = av.y;
    As[0][ak + 2][am] = av.z; As[0][ak + 3][am] = av.w;
    *(float4*)&Bs[0][bkr][bn8]     = bv0;
    *(float4*)&Bs[0][bkr][bn8 + 4] = bv1;
    __syncthreads();

    for (int it = 0; it < nIter; it++) {
        const int cur = it & 1;
        const int nxt = cur ^ 1;
        const bool more = (it + 1) < nIter;

        if (more) {
            const int k0 = (it + 1) * BKK;
            av  = *(const float4*)(Aptr + k0);
            bv0 = *(const float4*)(Bptr + (size_t)k0 * a.N);
            bv1 = *(const float4*)(Bptr + (size_t)k0 * a.N + 4);
        }

        #pragma unroll
        for (int k = 0; k < BKK; k++) {
            float4 a4 = *(const float4*)&As[cur][k][rowb];
            float4 b4 = *(const float4*)&Bs[cur][k][colb];
            float ar[4] = {a4.x, a4.y, a4.z, a4.w};
            float br[4] = {b4.x, b4.y, b4.z, b4.w};
            #pragma unroll
            for (int r = 0; r < 4; r++)
                #pragma unroll
                for (int c = 0; c < 4; c++)
                    acc[r][c] = fmaf(ar[r], br[c], acc[r][c]);
        }

        if (more) {
            As[nxt][ak + 0][am] = av.x; As[nxt][ak + 1][am] = av.y;
            As[nxt][ak + 2][am] = av.z; As[nxt][ak + 3][am] = av.w;
            *(float4*)&Bs[nxt][bkr][bn8]     = bv0;
            *(float4*)&Bs[nxt][bkr][bn8 + 4] = bv1;
            __syncthreads();
        }
    }

    float4 bb = {0.f, 0.f, 0.f, 0.f};
    if (bias) bb = *(const float4*)&bias[bn + colb];
    #pragma unroll
    for (int r = 0; r < 4; r++) {
        float4 o;
        o.x = acc[r][0] + bb.x;
        o.y = acc[r][1] + bb.y;
        o.z = acc[r][2] + bb.z;
        o.w = acc[r][3] + bb.w;
        if (a.relu) {
            o.x = fmaxf(o.x, 0.f); o.y = fmaxf(o.y, 0.f);
            o.z = fmaxf(o.z, 0.f); o.w = fmaxf(o.w, 0.f);
        }
        *(float4*)&C[(size_t)(bm + rowb + r) * a.N + bn + colb] = o;
    }
}

// ---------------------------------------------------------------------------
// Attention partials: grid (ROWS/4, JSPLIT=8), 256 threads = 4 rows x 64 dx4.
// __launch_bounds__(256, 4): cap regs at 64 -> 4 CTAs/SM (R12 profile showed
// 73 regs -> 3 CTAs/SM -> occ 34% -> DRAM stuck at 65%). Unroll 4 keeps the
// load pipeline inside the 64-reg budget without spills.
// ---------------------------------------------------------------------------
__global__ __launch_bounds__(256, 4)
void attn_part_kernel(const float* __restrict__ Q, const float* __restrict__ K,
                      const float* __restrict__ V, const float* __restrict__ e_add,
                      const float* __restrict__ e_mul,
                      const float* __restrict__ mask, float4* __restrict__ SA)
{
    const int tx  = threadIdx.x & 63;          // dx quad index 0..63
    const int ty  = threadIdx.x >> 6;          // 0..3 row within block
    const int row = blockIdx.x * 4 + ty;       // b*NN + i
    const int jz  = blockIdx.y;                // 0..7
    const int b   = row >> 8;
    const int dx  = tx * 4;
    const int j0  = jz * JCHUNK;

    const float scale = 0.17677669529663687f;  // 1/sqrt(32)
    const float mi = mask[row];

    float4 q4 = *(const float4*)&Q[(size_t)row * DX + dx];
    const float qs = mi * scale;
    q4.x *= qs; q4.y *= qs; q4.z *= qs; q4.w *= qs;

    const float* __restrict__ ea = e_add + ((size_t)row * NN + j0) * DX + dx;
    const float* __restrict__ em = e_mul + ((size_t)row * NN + j0) * DX + dx;
    const float* __restrict__ kb = K + ((size_t)b * NN + j0) * DX + dx;
    const float* __restrict__ vb = V + ((size_t)b * NN + j0) * DX + dx;
    const float* __restrict__ mrow = mask + b * NN + j0;

    float4 s   = {0.f, 0.f, 0.f, 0.f};
    float4 acc = {0.f, 0.f, 0.f, 0.f};

    #pragma unroll 4
    for (int j = 0; j < JCHUNK; j++) {
        const float mj = mrow[j];
        const float ee = mi * mj;
        const size_t o = (size_t)j * DX;
        float4 em4, ea4;
        asm("ld.global.cs.v4.f32 {%0,%1,%2,%3}, [%4];"
            : "=f"(em4.x), "=f"(em4.y), "=f"(em4.z), "=f"(em4.w) : "l"(em + o));
        asm("ld.global.cs.v4.f32 {%0,%1,%2,%3}, [%4];"
            : "=f"(ea4.x), "=f"(ea4.y), "=f"(ea4.z), "=f"(ea4.w) : "l"(ea + o));
        float4 k4 = *(const float4*)(kb + o);
        float4 v4 = *(const float4*)(vb + o);

        float yx = fmaf(q4.x * k4.x, fmaf(em4.x, ee, 1.f), ea4.x * ee);
        float yy = fmaf(q4.y * k4.y, fmaf(em4.y, ee, 1.f), ea4.y * ee);
        float yz = fmaf(q4.z * k4.z, fmaf(em4.z, ee, 1.f), ea4.z * ee);
        float yw = fmaf(q4.w * k4.w, fmaf(em4.w, ee, 1.f), ea4.w * ee);

        float px = __expf(yx - 10.f) * mj;
        float py = __expf(yy - 10.f) * mj;
        float pz = __expf(yz - 10.f) * mj;
        float pw = __expf(yw - 10.f) * mj;

        s.x += px; s.y += py; s.z += pz; s.w += pw;
        acc.x = fmaf(px, v4.x, acc.x);
        acc.y = fmaf(py, v4.y, acc.y);
        acc.z = fmaf(pz, v4.z, acc.z);
        acc.w = fmaf(pw, v4.w, acc.w);
    }

    const size_t so = (((size_t)jz * ROWS + row) * 64 + tx) * 2;
    SA[so]     = s;
    SA[so + 1] = acc;
}

// ---------------------------------------------------------------------------
// Combine attn partials -> T = y_add + (y_mul+1) * (sum acc / sum s)
// ---------------------------------------------------------------------------
__global__ __launch_bounds__(256)
void attn_combine_kernel(const float4* __restrict__ SA,
                         const float* __restrict__ y_add,
                         const float* __restrict__ y_mul,
                         float* __restrict__ T)
{
    const int tx  = threadIdx.x & 63;
    const int ty  = threadIdx.x >> 6;
    const int row = blockIdx.x * 4 + ty;
    const int b   = row >> 8;
    const int dx  = tx * 4;

    float4 s   = {0.f, 0.f, 0.f, 0.f};
    float4 acc = {0.f, 0.f, 0.f, 0.f};
    #pragma unroll
    for (int jz = 0; jz < JSPLIT; jz++) {
        const size_t so = (((size_t)jz * ROWS + row) * 64 + tx) * 2;
        float4 ps = SA[so];
        float4 pa = SA[so + 1];
        s.x += ps.x; s.y += ps.y; s.z += ps.z; s.w += ps.w;
        acc.x += pa.x; acc.y += pa.y; acc.z += pa.z; acc.w += pa.w;
    }

    float4 ya = *(const float4*)&y_add[b * DX + dx];
    float4 ym = *(const float4*)&y_mul[b * DX + dx];
    float4 o;
    o.x = fmaf(ym.x + 1.f, acc.x / s.x, ya.x);
    o.y = fmaf(ym.y + 1.f, acc.y / s.y, ya.y);
    o.z = fmaf(ym.z + 1.f, acc.z / s.z, ya.z);
    o.w = fmaf(ym.w + 1.f, acc.w / s.w, ya.w);
    *(float4*)&T[(size_t)row * DX + dx] = o;
}

// ---------------------------------------------------------------------------
// Warp-per-row fused split-K reduce + bias + residual + LayerNorm.
// ---------------------------------------------------------------------------
__global__ __launch_bounds__(256)
void ln_kernel(const float* __restrict__ base, const float* __restrict__ P,
               int nsplit, const float* __restrict__ bias,
               const float* __restrict__ mask,
               const float* __restrict__ g, const float* __restrict__ beta,
               float* __restrict__ out)
{
    const int w    = threadIdx.x >> 5;
    const int lane = threadIdx.x & 31;
    const int row  = blockIdx.x * 8 + w;
    const int col  = lane * 8;
    const size_t MN = (size_t)ROWS * DX;
    const size_t off = (size_t)row * DX + col;

    float4 a0 = *(const float4*)&bias[col];
    float4 a1 = *(const float4*)&bias[col + 4];
    for (int z = 0; z < nsplit; z++) {
        float4 p0 = *(const float4*)&P[z * MN + off];
        float4 p1 = *(const float4*)&P[z * MN + off + 4];
        a0.x += p0.x; a0.y += p0.y; a0.z += p0.z; a0.w += p0.w;
        a1.x += p1.x; a1.y += p1.y; a1.z += p1.z; a1.w += p1.w;
    }

    const float mrow = mask ? mask[row] : 1.f;
    float4 b0 = *(const float4*)&base[off];
    float4 b1 = *(const float4*)&base[off + 4];
    float v[8];
    v[0] = fmaf(a0.x, mrow, b0.x); v[1] = fmaf(a0.y, mrow, b0.y);
    v[2] = fmaf(a0.z, mrow, b0.z); v[3] = fmaf(a0.w, mrow, b0.w);
    v[4] = fmaf(a1.x, mrow, b1.x); v[5] = fmaf(a1.y, mrow, b1.y);
    v[6] = fmaf(a1.z, mrow, b1.z); v[7] = fmaf(a1.w, mrow, b1.w);

    float s1 = 0.f, s2 = 0.f;
    #pragma unroll
    for (int i = 0; i < 8; i++) { s1 += v[i]; s2 = fmaf(v[i], v[i], s2); }
    #pragma unroll
    for (int o = 16; o > 0; o >>= 1) {
        s1 += __shfl_xor_sync(0xffffffffu, s1, o);
        s2 += __shfl_xor_sync(0xffffffffu, s2, o);
    }

    const float mu  = s1 * (1.f / DX);
    const float var = s2 * (1.f / DX) - mu * mu;
    const float rs  = rsqrtf(var + EPS);

    float4 g0 = *(const float4*)&g[col];
    float4 g1 = *(const float4*)&g[col + 4];
    float4 t0 = *(const float4*)&beta[col];
    float4 t1 = *(const float4*)&beta[col + 4];
    float4 o0, o1;
    o0.x = fmaf((v[0] - mu) * rs, g0.x, t0.x);
    o0.y = fmaf((v[1] - mu) * rs, g0.y, t0.y);
    o0.z = fmaf((v[2] - mu) * rs, g0.z, t0.z);
    o0.w = fmaf((v[3] - mu) * rs, g0.w, t0.w);
    o1.x = fmaf((v[4] - mu) * rs, g1.x, t1.x);
    o1.y = fmaf((v[5] - mu) * rs, g1.y, t1.y);
    o1.z = fmaf((v[6] - mu) * rs, g1.z, t1.z);
    o1.w = fmaf((v[7] - mu) * rs, g1.w, t1.w);
    *(float4*)&out[off]     = o0;
    *(float4*)&out[off + 4] = o1;
}

// ---------------------------------------------------------------------------
// Launch (strictly serial, single stream)
// ---------------------------------------------------------------------------
extern "C" void kernel_launch(void* const* d_in, const int* in_sizes, int n_in,
                              void* d_out, int out_size)
{
    const float* X       = (const float*)d_in[0];
    const float* e_add   = (const float*)d_in[1];
    const float* e_mul   = (const float*)d_in[2];
    const float* y_x_add = (const float*)d_in[3];
    const float* y_x_mul = (const float*)d_in[4];
    const float* nmask   = (const float*)d_in[5];
    const float* Wq      = (const float*)d_in[6];
    const float* bq      = (const float*)d_in[7];
    const float* Wk      = (const float*)d_in[8];
    const float* bk      = (const float*)d_in[9];
    const float* Wv      = (const float*)d_in[10];
    const float* bv      = (const float*)d_in[11];
    const float* Wo      = (const float*)d_in[12];
    const float* bo      = (const float*)d_in[13];
    const float* W1      = (const float*)d_in[14];
    const float* b1      = (const float*)d_in[15];
    const float* W2      = (const float*)d_in[16];
    const float* b2      = (const float*)d_in[17];
    const float* g1      = (const float*)d_in[18];
    const float* beta1   = (const float*)d_in[19];
    const float* g2      = (const float*)d_in[20];
    const float* beta2   = (const float*)d_in[21];
    float* out = (float*)d_out;

    float *Qb, *Kb, *Vb, *Tb, *X1b, *Hb, *Pb;
    float4* SAb;
    cudaGetSymbolAddress((void**)&Qb,  g_Q);
    cudaGetSymbolAddress((void**)&Kb,  g_K);
    cudaGetSymbolAddress((void**)&Vb,  g_V);
    cudaGetSymbolAddress((void**)&Tb,  g_T);
    cudaGetSymbolAddress((void**)&X1b, g_X1);
    cudaGetSymbolAddress((void**)&Hb,  g_H);
    cudaGetSymbolAddress((void**)&Pb,  g_P);
    cudaGetSymbolAddress((void**)&SAb, g_SA);

    // 1) QKV projections, fused along N (384 CTAs)
    {
        GArgs a = {};
        a.A = X;
        a.B[0] = Wq; a.B[1] = Wk; a.B[2] = Wv;
        a.bias[0] = bq; a.bias[1] = bk; a.bias[2] = bv;
        a.C[0] = Qb; a.C[1] = Kb; a.C[2] = Vb;
        a.M = ROWS; a.N = DX; a.lda = DX; a.kPerZ = DX; a.relu = 0; a.mode = 0;
        dim3 grid(3 * DX / BN, ROWS / BM, 1);
        sgemm_kernel<<<grid, 128>>>(a);
    }

    // 2-3) fillers so attn_part lands in ncu's sampled launch slot (#4)
    noop_kernel<<<1, 32>>>();
    noop_kernel<<<1, 32>>>();

    // 4) attention partials (2048 CTAs, 64-reg cap -> 4 CTAs/SM)
    {
        dim3 grid(ROWS / 4, JSPLIT);
        attn_part_kernel<<<grid, 256>>>(Qb, Kb, Vb, e_add, e_mul, nmask, SAb);
    }
    attn_combine_kernel<<<ROWS / 4, 256>>>(SAb, y_x_add, y_x_mul, Tb);

    // 5) Wo partials (split-K=4, 512 CTAs); bias folded into LN1
    {
        GArgs a = {};
        a.A = Tb; a.B[0] = Wo; a.C[0] = Pb;
        a.M = ROWS; a.N = DX; a.lda = DX; a.kPerZ = DX / 4; a.relu = 0; a.mode = 1;
        dim3 grid(DX / BN, ROWS / BM, 4);
        sgemm_kernel<<<grid, 128>>>(a);
    }

    // 6) X1 = LN(X + mask*(sum P + bo))   (warp-per-row, 128 CTAs)
    ln_kernel<<<ROWS / 8, 256>>>(X, Pb, 4, bo, nmask, g1, beta1, X1b);

    // 7) H = relu(X1 @ W1 + b1)  (512 CTAs)
    {
        GArgs a = {};
        a.A = X1b; a.B[0] = W1; a.bias[0] = b1; a.C[0] = Hb;
        a.M = ROWS; a.N = DFF; a.lda = DX; a.kPerZ = DX; a.relu = 1; a.mode = 0;
        dim3 grid(DFF / BN, ROWS / BM, 1);
        sgemm_kernel<<<grid, 128>>>(a);
    }

    // 8) W2 partials (split-K=8, 1024 CTAs); bias folded into LN2
    {
        GArgs a = {};
        a.A = Hb; a.B[0] = W2; a.C[0] = Pb;
        a.M = ROWS; a.N = DX; a.lda = DFF; a.kPerZ = DFF / 8; a.relu = 0; a.mode = 1;
        dim3 grid(DX / BN, ROWS / BM, 8);
        sgemm_kernel<<<grid, 128>>>(a);
    }

    // 9) out = LN(X1 + sum P + b2)   (warp-per-row, 128 CTAs)
    ln_kernel<<<ROWS / 8, 256>>>(X1b, Pb, 8, b2, (const float*)nullptr,
                                 g2, beta2, out);
}

// round 15
// speedup vs baseline: 1.2514x; 1.2514x over previous
#include <cuda_runtime.h>
#include <cuda_bf16.h>
#include <math.h>
#include <stdint.h>

// ---------------------------------------------------------------------------
// Problem constants
// ---------------------------------------------------------------------------
#define BS 4
#define NN 256
#define DX 256
#define HH 8
#define DF 32
#define DFF 1024
#define ROWS (BS * NN)            // 1024
#define EPS 1e-5f
#define JSPLIT 8
#define JCHUNK (NN / JSPLIT)      // 32

// ---------------------------------------------------------------------------
// Device scratch (no allocations allowed)
// ---------------------------------------------------------------------------
__device__ float g_Q [ROWS * DX];
__device__ float g_K [ROWS * DX];
__device__ float g_V [ROWS * DX];
__device__ float g_T [ROWS * DX];
__device__ float g_X1[ROWS * DX];
__device__ float g_H [ROWS * DFF];
__device__ float g_P [8 * ROWS * DX];                  // split-K partials
__device__ float4 g_SA[JSPLIT * ROWS * (DX / 4) * 2];  // attn partials (s4, acc4)
__device__ float g_dummy;

// ---------------------------------------------------------------------------
// No-op filler (keeps ncu's sampled launch slot aligned with attn_part).
// ---------------------------------------------------------------------------
__global__ void noop_kernel() { if (threadIdx.x == 0) g_dummy = 1.0f; }

// ---------------------------------------------------------------------------
// Double-buffered SGEMM: BM=32, BN=64, BK=16, 128 threads, 4x4 micro-tile,
// ping-pong SMEM, 1 sync/iter.
// mode 0: fused-N (blockIdx.x spans matrices; bias added here)
// mode 1: split-K (blockIdx.z = K-chunk; partial to C + z*M*N; bias deferred)
// ---------------------------------------------------------------------------
struct GArgs {
    const float* A;
    const float* B[3];
    const float* bias[3];
    float* C[3];
    int M, N, lda;
    int kPerZ;
    int relu, mode;
};

#define BM 32
#define BN 64
#define BKK 16

__global__ __launch_bounds__(128)
void sgemm_kernel(GArgs a)
{
    __shared__ __align__(16) float As[2][BKK][BM];
    __shared__ __align__(16) float Bs[2][BKK][BN];

    const int tid = threadIdx.x;

    const float* __restrict__ B;
    const float* bias;
    float* C;
    int kStart, bn;
    if (a.mode == 1) {
        B = a.B[0]; bias = nullptr;
        C = a.C[0] + (size_t)blockIdx.z * a.M * a.N;
        kStart = blockIdx.z * a.kPerZ;
        bn = blockIdx.x * BN;
    } else {
        const int tilesPerMat = a.N / BN;
        const int sel = blockIdx.x / tilesPerMat;
        B = a.B[sel]; bias = a.bias[sel]; C = a.C[sel];
        kStart = 0;
        bn = (blockIdx.x - sel * tilesPerMat) * BN;
    }
    const int bm = blockIdx.y * BM;

    const int colb = (tid & 15) * 4;
    const int rowb = (tid >> 4) * 4;
    const int am = tid >> 2;
    const int ak = (tid & 3) * 4;
    const int bkr = tid >> 3;
    const int bn8 = (tid & 7) * 8;

    const float* Aptr = a.A + (size_t)(bm + am) * a.lda + kStart + ak;
    const float* Bptr = B + (size_t)(kStart + bkr) * a.N + bn + bn8;

    float acc[4][4] = {};
    const int nIter = a.kPerZ / BKK;

    float4 av  = *(const float4*)(Aptr);
    float4 bv0 = *(const float4*)(Bptr);
    float4 bv1 = *(const float4*)(Bptr + 4);
    As[0][ak + 0][am] = av.x; As[0][ak + 1][am] = av.y;
    As[0][ak + 2][am] = av.z; As[0][ak + 3][am] = av.w;
    *(float4*)&Bs[0][bkr][bn8]     = bv0;
    *(float4*)&Bs[0][bkr][bn8 + 4] = bv1;
    __syncthreads();

    for (int it = 0; it < nIter; it++) {
        const int cur = it & 1;
        const int nxt = cur ^ 1;
        const bool more = (it + 1) < nIter;

        if (more) {
            const int k0 = (it + 1) * BKK;
            av  = *(const float4*)(Aptr + k0);
            bv0 = *(const float4*)(Bptr + (size_t)k0 * a.N);
            bv1 = *(const float4*)(Bptr + (size_t)k0 * a.N + 4);
        }

        #pragma unroll
        for (int k = 0; k < BKK; k++) {
            float4 a4 = *(const float4*)&As[cur][k][rowb];
            float4 b4 = *(const float4*)&Bs[cur][k][colb];
            float ar[4] = {a4.x, a4.y, a4.z, a4.w};
            float br[4] = {b4.x, b4.y, b4.z, b4.w};
            #pragma unroll
            for (int r = 0; r < 4; r++)
                #pragma unroll
                for (int c = 0; c < 4; c++)
                    acc[r][c] = fmaf(ar[r], br[c], acc[r][c]);
        }

        if (more) {
            As[nxt][ak + 0][am] = av.x; As[nxt][ak + 1][am] = av.y;
            As[nxt][ak + 2][am] = av.z; As[nxt][ak + 3][am] = av.w;
            *(float4*)&Bs[nxt][bkr][bn8]     = bv0;
            *(float4*)&Bs[nxt][bkr][bn8 + 4] = bv1;
            __syncthreads();
        }
    }

    float4 bb = {0.f, 0.f, 0.f, 0.f};
    if (bias) bb = *(const float4*)&bias[bn + colb];
    #pragma unroll
    for (int r = 0; r < 4; r++) {
        float4 o;
        o.x = acc[r][0] + bb.x;
        o.y = acc[r][1] + bb.y;
        o.z = acc[r][2] + bb.z;
        o.w = acc[r][3] + bb.w;
        if (a.relu) {
            o.x = fmaxf(o.x, 0.f); o.y = fmaxf(o.y, 0.f);
            o.z = fmaxf(o.z, 0.f); o.w = fmaxf(o.w, 0.f);
        }
        *(float4*)&C[(size_t)(bm + rowb + r) * a.N + bn + colb] = o;
    }
}

// ---------------------------------------------------------------------------
// Attention partials with SMEM-staged K/V: grid (ROWS/4, JSPLIT=8),
// 256 threads = 4 rows x 64 dx4. The 4 rows share K/V; stage the CTA's
// 32j x 256dx K/V slab (64KB) in SMEM once, then the hot loop issues only
// the two e-stream LDG.128s per j (full queue for the DRAM stream).
// No reg cap (R13 spills lesson), unroll 8 (R12 winner).
// ---------------------------------------------------------------------------
#define KV4 (JCHUNK * DX / 4)     // 2048 float4 per tensor

__global__ __launch_bounds__(256)
void attn_part_kernel(const float* __restrict__ Q, const float* __restrict__ K,
                      const float* __restrict__ V, const float* __restrict__ e_add,
                      const float* __restrict__ e_mul,
                      const float* __restrict__ mask, float4* __restrict__ SA)
{
    extern __shared__ float4 skv[];            // [0,2048)=K, [2048,4096)=V
    float4* sK4 = skv;
    float4* sV4 = skv + KV4;

    const int tx  = threadIdx.x & 63;          // dx quad index 0..63
    const int ty  = threadIdx.x >> 6;          // 0..3 row within block
    const int row = blockIdx.x * 4 + ty;       // b*NN + i
    const int jz  = blockIdx.y;                // 0..7
    const int b   = row >> 8;
    const int dx  = tx * 4;
    const int j0  = jz * JCHUNK;

    // cooperative K/V stage (same for all 4 rows: same batch b)
    {
        const float4* gK = (const float4*)(K + ((size_t)b * NN + j0) * DX);
        const float4* gV = (const float4*)(V + ((size_t)b * NN + j0) * DX);
        #pragma unroll
        for (int i = 0; i < KV4 / 256; i++) {
            const int p = i * 256 + threadIdx.x;
            sK4[p] = gK[p];
            sV4[p] = gV[p];
        }
    }
    __syncthreads();

    const float scale = 0.17677669529663687f;  // 1/sqrt(32)
    const float mi = mask[row];

    float4 q4 = *(const float4*)&Q[(size_t)row * DX + dx];
    const float qs = mi * scale;
    q4.x *= qs; q4.y *= qs; q4.z *= qs; q4.w *= qs;

    const float* __restrict__ ea = e_add + ((size_t)row * NN + j0) * DX + dx;
    const float* __restrict__ em = e_mul + ((size_t)row * NN + j0) * DX + dx;
    const float* __restrict__ mrow = mask + b * NN + j0;

    float4 s   = {0.f, 0.f, 0.f, 0.f};
    float4 acc = {0.f, 0.f, 0.f, 0.f};

    #pragma unroll 8
    for (int j = 0; j < JCHUNK; j++) {
        const float mj = mrow[j];
        const float ee = mi * mj;
        const size_t o = (size_t)j * DX;
        float4 em4, ea4;
        asm("ld.global.cs.v4.f32 {%0,%1,%2,%3}, [%4];"
            : "=f"(em4.x), "=f"(em4.y), "=f"(em4.z), "=f"(em4.w) : "l"(em + o));
        asm("ld.global.cs.v4.f32 {%0,%1,%2,%3}, [%4];"
            : "=f"(ea4.x), "=f"(ea4.y), "=f"(ea4.z), "=f"(ea4.w) : "l"(ea + o));
        float4 k4 = sK4[j * 64 + tx];
        float4 v4 = sV4[j * 64 + tx];

        float yx = fmaf(q4.x * k4.x, fmaf(em4.x, ee, 1.f), ea4.x * ee);
        float yy = fmaf(q4.y * k4.y, fmaf(em4.y, ee, 1.f), ea4.y * ee);
        float yz = fmaf(q4.z * k4.z, fmaf(em4.z, ee, 1.f), ea4.z * ee);
        float yw = fmaf(q4.w * k4.w, fmaf(em4.w, ee, 1.f), ea4.w * ee);

        float px = __expf(yx - 10.f) * mj;
        float py = __expf(yy - 10.f) * mj;
        float pz = __expf(yz - 10.f) * mj;
        float pw = __expf(yw - 10.f) * mj;

        s.x += px; s.y += py; s.z += pz; s.w += pw;
        acc.x = fmaf(px, v4.x, acc.x);
        acc.y = fmaf(py, v4.y, acc.y);
        acc.z = fmaf(pz, v4.z, acc.z);
        acc.w = fmaf(pw, v4.w, acc.w);
    }

    const size_t so = (((size_t)jz * ROWS + row) * 64 + tx) * 2;
    SA[so]     = s;
    SA[so + 1] = acc;
}

// ---------------------------------------------------------------------------
// Combine attn partials -> T = y_add + (y_mul+1) * (sum acc / sum s)
// ---------------------------------------------------------------------------
__global__ __launch_bounds__(256)
void attn_combine_kernel(const float4* __restrict__ SA,
                         const float* __restrict__ y_add,
                         const float* __restrict__ y_mul,
                         float* __restrict__ T)
{
    const int tx  = threadIdx.x & 63;
    const int ty  = threadIdx.x >> 6;
    const int row = blockIdx.x * 4 + ty;
    const int b   = row >> 8;
    const int dx  = tx * 4;

    float4 s   = {0.f, 0.f, 0.f, 0.f};
    float4 acc = {0.f, 0.f, 0.f, 0.f};
    #pragma unroll
    for (int jz = 0; jz < JSPLIT; jz++) {
        const size_t so = (((size_t)jz * ROWS + row) * 64 + tx) * 2;
        float4 ps = SA[so];
        float4 pa = SA[so + 1];
        s.x += ps.x; s.y += ps.y; s.z += ps.z; s.w += ps.w;
        acc.x += pa.x; acc.y += pa.y; acc.z += pa.z; acc.w += pa.w;
    }

    float4 ya = *(const float4*)&y_add[b * DX + dx];
    float4 ym = *(const float4*)&y_mul[b * DX + dx];
    float4 o;
    o.x = fmaf(ym.x + 1.f, acc.x / s.x, ya.x);
    o.y = fmaf(ym.y + 1.f, acc.y / s.y, ya.y);
    o.z = fmaf(ym.z + 1.f, acc.z / s.z, ya.z);
    o.w = fmaf(ym.w + 1.f, acc.w / s.w, ya.w);
    *(float4*)&T[(size_t)row * DX + dx] = o;
}

// ---------------------------------------------------------------------------
// Warp-per-row fused split-K reduce + bias + residual + LayerNorm.
// ---------------------------------------------------------------------------
__global__ __launch_bounds__(256)
void ln_kernel(const float* __restrict__ base, const float* __restrict__ P,
               int nsplit, const float* __restrict__ bias,
               const float* __restrict__ mask,
               const float* __restrict__ g, const float* __restrict__ beta,
               float* __restrict__ out)
{
    const int w    = threadIdx.x >> 5;
    const int lane = threadIdx.x & 31;
    const int row  = blockIdx.x * 8 + w;
    const int col  = lane * 8;
    const size_t MN = (size_t)ROWS * DX;
    const size_t off = (size_t)row * DX + col;

    float4 a0 = *(const float4*)&bias[col];
    float4 a1 = *(const float4*)&bias[col + 4];
    for (int z = 0; z < nsplit; z++) {
        float4 p0 = *(const float4*)&P[z * MN + off];
        float4 p1 = *(const float4*)&P[z * MN + off + 4];
        a0.x += p0.x; a0.y += p0.y; a0.z += p0.z; a0.w += p0.w;
        a1.x += p1.x; a1.y += p1.y; a1.z += p1.z; a1.w += p1.w;
    }

    const float mrow = mask ? mask[row] : 1.f;
    float4 b0 = *(const float4*)&base[off];
    float4 b1 = *(const float4*)&base[off + 4];
    float v[8];
    v[0] = fmaf(a0.x, mrow, b0.x); v[1] = fmaf(a0.y, mrow, b0.y);
    v[2] = fmaf(a0.z, mrow, b0.z); v[3] = fmaf(a0.w, mrow, b0.w);
    v[4] = fmaf(a1.x, mrow, b1.x); v[5] = fmaf(a1.y, mrow, b1.y);
    v[6] = fmaf(a1.z, mrow, b1.z); v[7] = fmaf(a1.w, mrow, b1.w);

    float s1 = 0.f, s2 = 0.f;
    #pragma unroll
    for (int i = 0; i < 8; i++) { s1 += v[i]; s2 = fmaf(v[i], v[i], s2); }
    #pragma unroll
    for (int o = 16; o > 0; o >>= 1) {
        s1 += __shfl_xor_sync(0xffffffffu, s1, o);
        s2 += __shfl_xor_sync(0xffffffffu, s2, o);
    }

    const float mu  = s1 * (1.f / DX);
    const float var = s2 * (1.f / DX) - mu * mu;
    const float rs  = rsqrtf(var + EPS);

    float4 g0 = *(const float4*)&g[col];
    float4 g1 = *(const float4*)&g[col + 4];
    float4 t0 = *(const float4*)&beta[col];
    float4 t1 = *(const float4*)&beta[col + 4];
    float4 o0, o1;
    o0.x = fmaf((v[0] - mu) * rs, g0.x, t0.x);
    o0.y = fmaf((v[1] - mu) * rs, g0.y, t0.y);
    o0.z = fmaf((v[2] - mu) * rs, g0.z, t0.z);
    o0.w = fmaf((v[3] - mu) * rs, g0.w, t0.w);
    o1.x = fmaf((v[4] - mu) * rs, g1.x, t1.x);
    o1.y = fmaf((v[5] - mu) * rs, g1.y, t1.y);
    o1.z = fmaf((v[6] - mu) * rs, g1.z, t1.z);
    o1.w = fmaf((v[7] - mu) * rs, g1.w, t1.w);
    *(float4*)&out[off]     = o0;
    *(float4*)&out[off + 4] = o1;
}

// ---------------------------------------------------------------------------
// Launch (strictly serial, single stream)
// ---------------------------------------------------------------------------
extern "C" void kernel_launch(void* const* d_in, const int* in_sizes, int n_in,
                              void* d_out, int out_size)
{
    const float* X       = (const float*)d_in[0];
    const float* e_add   = (const float*)d_in[1];
    const float* e_mul   = (const float*)d_in[2];
    const float* y_x_add = (const float*)d_in[3];
    const float* y_x_mul = (const float*)d_in[4];
    const float* nmask   = (const float*)d_in[5];
    const float* Wq      = (const float*)d_in[6];
    const float* bq      = (const float*)d_in[7];
    const float* Wk      = (const float*)d_in[8];
    const float* bk      = (const float*)d_in[9];
    const float* Wv      = (const float*)d_in[10];
    const float* bv      = (const float*)d_in[11];
    const float* Wo      = (const float*)d_in[12];
    const float* bo      = (const float*)d_in[13];
    const float* W1      = (const float*)d_in[14];
    const float* b1      = (const float*)d_in[15];
    const float* W2      = (const float*)d_in[16];
    const float* b2      = (const float*)d_in[17];
    const float* g1      = (const float*)d_in[18];
    const float* beta1   = (const float*)d_in[19];
    const float* g2      = (const float*)d_in[20];
    const float* beta2   = (const float*)d_in[21];
    float* out = (float*)d_out;

    float *Qb, *Kb, *Vb, *Tb, *X1b, *Hb, *Pb;
    float4* SAb;
    cudaGetSymbolAddress((void**)&Qb,  g_Q);
    cudaGetSymbolAddress((void**)&Kb,  g_K);
    cudaGetSymbolAddress((void**)&Vb,  g_V);
    cudaGetSymbolAddress((void**)&Tb,  g_T);
    cudaGetSymbolAddress((void**)&X1b, g_X1);
    cudaGetSymbolAddress((void**)&Hb,  g_H);
    cudaGetSymbolAddress((void**)&Pb,  g_P);
    cudaGetSymbolAddress((void**)&SAb, g_SA);

    const int kvSmem = 2 * KV4 * sizeof(float4);   // 64KB
    static int smemSet = 0;
    if (!smemSet) {
        cudaFuncSetAttribute(attn_part_kernel,
                             cudaFuncAttributeMaxDynamicSharedMemorySize, kvSmem);
        smemSet = 1;
    }

    // 1) QKV projections, fused along N (384 CTAs)
    {
        GArgs a = {};
        a.A = X;
        a.B[0] = Wq; a.B[1] = Wk; a.B[2] = Wv;
        a.bias[0] = bq; a.bias[1] = bk; a.bias[2] = bv;
        a.C[0] = Qb; a.C[1] = Kb; a.C[2] = Vb;
        a.M = ROWS; a.N = DX; a.lda = DX; a.kPerZ = DX; a.relu = 0; a.mode = 0;
        dim3 grid(3 * DX / BN, ROWS / BM, 1);
        sgemm_kernel<<<grid, 128>>>(a);
    }

    // 2-3) fillers so attn_part lands in ncu's sampled launch slot (#4)
    noop_kernel<<<1, 32>>>();
    noop_kernel<<<1, 32>>>();

    // 4) attention partials (2048 CTAs, SMEM-staged K/V)
    {
        dim3 grid(ROWS / 4, JSPLIT);
        attn_part_kernel<<<grid, 256, kvSmem>>>(Qb, Kb, Vb, e_add, e_mul,
                                                nmask, SAb);
    }
    attn_combine_kernel<<<ROWS / 4, 256>>>(SAb, y_x_add, y_x_mul, Tb);

    // 5) Wo partials (split-K=4, 512 CTAs); bias folded into LN1
    {
        GArgs a = {};
        a.A = Tb; a.B[0] = Wo; a.C[0] = Pb;
        a.M = ROWS; a.N = DX; a.lda = DX; a.kPerZ = DX / 4; a.relu = 0; a.mode = 1;
        dim3 grid(DX / BN, ROWS / BM, 4);
        sgemm_kernel<<<grid, 128>>>(a);
    }

    // 6) X1 = LN(X + mask*(sum P + bo))   (warp-per-row, 128 CTAs)
    ln_kernel<<<ROWS / 8, 256>>>(X, Pb, 4, bo, nmask, g1, beta1, X1b);

    // 7) H = relu(X1 @ W1 + b1)  (512 CTAs)
    {
        GArgs a = {};
        a.A = X1b; a.B[0] = W1; a.bias[0] = b1; a.C[0] = Hb;
        a.M = ROWS; a.N = DFF; a.lda = DX; a.kPerZ = DX; a.relu = 1; a.mode = 0;
        dim3 grid(DFF / BN, ROWS / BM, 1);
        sgemm_kernel<<<grid, 128>>>(a);
    }

    // 8) W2 partials (split-K=8, 1024 CTAs); bias folded into LN2
    {
        GArgs a = {};
        a.A = Hb; a.B[0] = W2; a.C[0] = Pb;
        a.M = ROWS; a.N = DX; a.lda = DFF; a.kPerZ = DFF / 8; a.relu = 0; a.mode = 1;
        dim3 grid(DX / BN, ROWS / BM, 8);
        sgemm_kernel<<<grid, 128>>>(a);
    }

    // 9) out = LN(X1 + sum P + b2)   (warp-per-row, 128 CTAs)
    ln_kernel<<<ROWS / 8, 256>>>(X1b, Pb, 8, b2, (const float*)nullptr,
                                 g2, beta2, out);
}

// round 16
// speedup vs baseline: 1.2936x; 1.0338x over previous
#include <cuda_runtime.h>
#include <cuda_bf16.h>
#include <math.h>
#include <stdint.h>

// ---------------------------------------------------------------------------
// Problem constants
// ---------------------------------------------------------------------------
#define BS 4
#define NN 256
#define DX 256
#define HH 8
#define DF 32
#define DFF 1024
#define ROWS (BS * NN)            // 1024
#define EPS 1e-5f
#define JSPLIT 8
#define JCHUNK (NN / JSPLIT)      // 32

// ---------------------------------------------------------------------------
// Device scratch (no allocations allowed)
// ---------------------------------------------------------------------------
__device__ float g_Q [ROWS * DX];
__device__ float g_K [ROWS * DX];
__device__ float g_V [ROWS * DX];
__device__ float g_T [ROWS * DX];
__device__ float g_X1[ROWS * DX];
__device__ float g_H [ROWS * DFF];
__device__ float g_P [4 * ROWS * DX];                  // split-K partials
__device__ float4 g_SA[JSPLIT * ROWS * (DX / 4) * 2];  // attn partials (s4, acc4)

// ---------------------------------------------------------------------------
// Double-buffered SGEMM: BM=32, BN=64, BK=16, 128 threads, 4x4 micro-tile,
// ping-pong SMEM, 1 sync/iter.
// mode 0: fused-N (blockIdx.x spans matrices; bias added here)
// mode 1: split-K (blockIdx.z = K-chunk; partial to C + z*M*N; bias deferred)
// ---------------------------------------------------------------------------
struct GArgs {
    const float* A;
    const float* B[3];
    const float* bias[3];
    float* C[3];
    int M, N, lda;
    int kPerZ;
    int relu, mode;
};

#define BM 32
#define BN 64
#define BKK 16

__global__ __launch_bounds__(128)
void sgemm_kernel(GArgs a)
{
    __shared__ __align__(16) float As[2][BKK][BM];
    __shared__ __align__(16) float Bs[2][BKK][BN];

    const int tid = threadIdx.x;

    const float* __restrict__ B;
    const float* bias;
    float* C;
    int kStart, bn;
    if (a.mode == 1) {
        B = a.B[0]; bias = nullptr;
        C = a.C[0] + (size_t)blockIdx.z * a.M * a.N;
        kStart = blockIdx.z * a.kPerZ;
        bn = blockIdx.x * BN;
    } else {
        const int tilesPerMat = a.N / BN;
        const int sel = blockIdx.x / tilesPerMat;
        B = a.B[sel]; bias = a.bias[sel]; C = a.C[sel];
        kStart = 0;
        bn = (blockIdx.x - sel * tilesPerMat) * BN;
    }
    const int bm = blockIdx.y * BM;

    const int colb = (tid & 15) * 4;
    const int rowb = (tid >> 4) * 4;
    const int am = tid >> 2;
    const int ak = (tid & 3) * 4;
    const int bkr = tid >> 3;
    const int bn8 = (tid & 7) * 8;

    const float* Aptr = a.A + (size_t)(bm + am) * a.lda + kStart + ak;
    const float* Bptr = B + (size_t)(kStart + bkr) * a.N + bn + bn8;

    float acc[4][4] = {};
    const int nIter = a.kPerZ / BKK;

    float4 av  = *(const float4*)(Aptr);
    float4 bv0 = *(const float4*)(Bptr);
    float4 bv1 = *(const float4*)(Bptr + 4);
    As[0][ak + 0][am] = av.x; As[0][ak + 1][am] = av.y;
    As[0][ak + 2][am] = av.z; As[0][ak + 3][am] = av.w;
    *(float4*)&Bs[0][bkr][bn8]     = bv0;
    *(float4*)&Bs[0][bkr][bn8 + 4] = bv1;
    __syncthreads();

    for (int it = 0; it < nIter; it++) {
        const int cur = it & 1;
        const int nxt = cur ^ 1;
        const bool more = (it + 1) < nIter;

        if (more) {
            const int k0 = (it + 1) * BKK;
            av  = *(const float4*)(Aptr + k0);
            bv0 = *(const float4*)(Bptr + (size_t)k0 * a.N);
            bv1 = *(const float4*)(Bptr + (size_t)k0 * a.N + 4);
        }

        #pragma unroll
        for (int k = 0; k < BKK; k++) {
            float4 a4 = *(const float4*)&As[cur][k][rowb];
            float4 b4 = *(const float4*)&Bs[cur][k][colb];
            float ar[4] = {a4.x, a4.y, a4.z, a4.w};
            float br[4] = {b4.x, b4.y, b4.z, b4.w};
            #pragma unroll
            for (int r = 0; r < 4; r++)
                #pragma unroll
                for (int c = 0; c < 4; c++)
                    acc[r][c] = fmaf(ar[r], br[c], acc[r][c]);
        }

        if (more) {
            As[nxt][ak + 0][am] = av.x; As[nxt][ak + 1][am] = av.y;
            As[nxt][ak + 2][am] = av.z; As[nxt][ak + 3][am] = av.w;
            *(float4*)&Bs[nxt][bkr][bn8]     = bv0;
            *(float4*)&Bs[nxt][bkr][bn8 + 4] = bv1;
            __syncthreads();
        }
    }

    float4 bb = {0.f, 0.f, 0.f, 0.f};
    if (bias) bb = *(const float4*)&bias[bn + colb];
    #pragma unroll
    for (int r = 0; r < 4; r++) {
        float4 o;
        o.x = acc[r][0] + bb.x;
        o.y = acc[r][1] + bb.y;
        o.z = acc[r][2] + bb.z;
        o.w = acc[r][3] + bb.w;
        if (a.relu) {
            o.x = fmaxf(o.x, 0.f); o.y = fmaxf(o.y, 0.f);
            o.z = fmaxf(o.z, 0.f); o.w = fmaxf(o.w, 0.f);
        }
        *(float4*)&C[(size_t)(bm + rowb + r) * a.N + bn + colb] = o;
    }
}

// ---------------------------------------------------------------------------
// Attention partials: grid (ROWS/4, JSPLIT=8), 256 threads = 4 rows x 64 dx4.
// R12 configuration exactly (measured best: 105.3us, DRAM 65.4%):
// float4 loads, 524k threads, unroll 8, no reg cap, no smem staging.
// Fixed-shift softmax -> additive partials (s4, acc4).
// ---------------------------------------------------------------------------
__global__ __launch_bounds__(256)
void attn_part_kernel(const float* __restrict__ Q, const float* __restrict__ K,
                      const float* __restrict__ V, const float* __restrict__ e_add,
                      const float* __restrict__ e_mul,
                      const float* __restrict__ mask, float4* __restrict__ SA)
{
    const int tx  = threadIdx.x & 63;          // dx quad index 0..63
    const int ty  = threadIdx.x >> 6;          // 0..3 row within block
    const int row = blockIdx.x * 4 + ty;       // b*NN + i
    const int jz  = blockIdx.y;                // 0..7
    const int b   = row >> 8;
    const int dx  = tx * 4;
    const int j0  = jz * JCHUNK;

    const float scale = 0.17677669529663687f;  // 1/sqrt(32)
    const float mi = mask[row];

    float4 q4 = *(const float4*)&Q[(size_t)row * DX + dx];
    const float qs = mi * scale;
    q4.x *= qs; q4.y *= qs; q4.z *= qs; q4.w *= qs;

    const float* __restrict__ ea = e_add + ((size_t)row * NN + j0) * DX + dx;
    const float* __restrict__ em = e_mul + ((size_t)row * NN + j0) * DX + dx;
    const float* __restrict__ kb = K + ((size_t)b * NN + j0) * DX + dx;
    const float* __restrict__ vb = V + ((size_t)b * NN + j0) * DX + dx;
    const float* __restrict__ mrow = mask + b * NN + j0;

    float4 s   = {0.f, 0.f, 0.f, 0.f};
    float4 acc = {0.f, 0.f, 0.f, 0.f};

    #pragma unroll 8
    for (int j = 0; j < JCHUNK; j++) {
        const float mj = mrow[j];
        const float ee = mi * mj;
        const size_t o = (size_t)j * DX;
        float4 em4, ea4;
        asm("ld.global.cs.v4.f32 {%0,%1,%2,%3}, [%4];"
            : "=f"(em4.x), "=f"(em4.y), "=f"(em4.z), "=f"(em4.w) : "l"(em + o));
        asm("ld.global.cs.v4.f32 {%0,%1,%2,%3}, [%4];"
            : "=f"(ea4.x), "=f"(ea4.y), "=f"(ea4.z), "=f"(ea4.w) : "l"(ea + o));
        float4 k4 = *(const float4*)(kb + o);
        float4 v4 = *(const float4*)(vb + o);

        float yx = fmaf(q4.x * k4.x, fmaf(em4.x, ee, 1.f), ea4.x * ee);
        float yy = fmaf(q4.y * k4.y, fmaf(em4.y, ee, 1.f), ea4.y * ee);
        float yz = fmaf(q4.z * k4.z, fmaf(em4.z, ee, 1.f), ea4.z * ee);
        float yw = fmaf(q4.w * k4.w, fmaf(em4.w, ee, 1.f), ea4.w * ee);

        float px = __expf(yx - 10.f) * mj;
        float py = __expf(yy - 10.f) * mj;
        float pz = __expf(yz - 10.f) * mj;
        float pw = __expf(yw - 10.f) * mj;

        s.x += px; s.y += py; s.z += pz; s.w += pw;
        acc.x = fmaf(px, v4.x, acc.x);
        acc.y = fmaf(py, v4.y, acc.y);
        acc.z = fmaf(pz, v4.z, acc.z);
        acc.w = fmaf(pw, v4.w, acc.w);
    }

    const size_t so = (((size_t)jz * ROWS + row) * 64 + tx) * 2;
    SA[so]     = s;
    SA[so + 1] = acc;
}

// ---------------------------------------------------------------------------
// Combine attn partials -> T = y_add + (y_mul+1) * (sum acc / sum s)
// ---------------------------------------------------------------------------
__global__ __launch_bounds__(256)
void attn_combine_kernel(const float4* __restrict__ SA,
                         const float* __restrict__ y_add,
                         const float* __restrict__ y_mul,
                         float* __restrict__ T)
{
    const int tx  = threadIdx.x & 63;
    const int ty  = threadIdx.x >> 6;
    const int row = blockIdx.x * 4 + ty;
    const int b   = row >> 8;
    const int dx  = tx * 4;

    float4 s   = {0.f, 0.f, 0.f, 0.f};
    float4 acc = {0.f, 0.f, 0.f, 0.f};
    #pragma unroll
    for (int jz = 0; jz < JSPLIT; jz++) {
        const size_t so = (((size_t)jz * ROWS + row) * 64 + tx) * 2;
        float4 ps = SA[so];
        float4 pa = SA[so + 1];
        s.x += ps.x; s.y += ps.y; s.z += ps.z; s.w += ps.w;
        acc.x += pa.x; acc.y += pa.y; acc.z += pa.z; acc.w += pa.w;
    }

    float4 ya = *(const float4*)&y_add[b * DX + dx];
    float4 ym = *(const float4*)&y_mul[b * DX + dx];
    float4 o;
    o.x = fmaf(ym.x + 1.f, acc.x / s.x, ya.x);
    o.y = fmaf(ym.y + 1.f, acc.y / s.y, ya.y);
    o.z = fmaf(ym.z + 1.f, acc.z / s.z, ya.z);
    o.w = fmaf(ym.w + 1.f, acc.w / s.w, ya.w);
    *(float4*)&T[(size_t)row * DX + dx] = o;
}

// ---------------------------------------------------------------------------
// Warp-per-row fused split-K reduce + bias + residual + LayerNorm.
// ---------------------------------------------------------------------------
__global__ __launch_bounds__(256)
void ln_kernel(const float* __restrict__ base, const float* __restrict__ P,
               int nsplit, const float* __restrict__ bias,
               const float* __restrict__ mask,
               const float* __restrict__ g, const float* __restrict__ beta,
               float* __restrict__ out)
{
    const int w    = threadIdx.x >> 5;
    const int lane = threadIdx.x & 31;
    const int row  = blockIdx.x * 8 + w;
    const int col  = lane * 8;
    const size_t MN = (size_t)ROWS * DX;
    const size_t off = (size_t)row * DX + col;

    float4 a0 = *(const float4*)&bias[col];
    float4 a1 = *(const float4*)&bias[col + 4];
    for (int z = 0; z < nsplit; z++) {
        float4 p0 = *(const float4*)&P[z * MN + off];
        float4 p1 = *(const float4*)&P[z * MN + off + 4];
        a0.x += p0.x; a0.y += p0.y; a0.z += p0.z; a0.w += p0.w;
        a1.x += p1.x; a1.y += p1.y; a1.z += p1.z; a1.w += p1.w;
    }

    const float mrow = mask ? mask[row] : 1.f;
    float4 b0 = *(const float4*)&base[off];
    float4 b1 = *(const float4*)&base[off + 4];
    float v[8];
    v[0] = fmaf(a0.x, mrow, b0.x); v[1] = fmaf(a0.y, mrow, b0.y);
    v[2] = fmaf(a0.z, mrow, b0.z); v[3] = fmaf(a0.w, mrow, b0.w);
    v[4] = fmaf(a1.x, mrow, b1.x); v[5] = fmaf(a1.y, mrow, b1.y);
    v[6] = fmaf(a1.z, mrow, b1.z); v[7] = fmaf(a1.w, mrow, b1.w);

    float s1 = 0.f, s2 = 0.f;
    #pragma unroll
    for (int i = 0; i < 8; i++) { s1 += v[i]; s2 = fmaf(v[i], v[i], s2); }
    #pragma unroll
    for (int o = 16; o > 0; o >>= 1) {
        s1 += __shfl_xor_sync(0xffffffffu, s1, o);
        s2 += __shfl_xor_sync(0xffffffffu, s2, o);
    }

    const float mu  = s1 * (1.f / DX);
    const float var = s2 * (1.f / DX) - mu * mu;
    const float rs  = rsqrtf(var + EPS);

    float4 g0 = *(const float4*)&g[col];
    float4 g1 = *(const float4*)&g[col + 4];
    float4 t0 = *(const float4*)&beta[col];
    float4 t1 = *(const float4*)&beta[col + 4];
    float4 o0, o1;
    o0.x = fmaf((v[0] - mu) * rs, g0.x, t0.x);
    o0.y = fmaf((v[1] - mu) * rs, g0.y, t0.y);
    o0.z = fmaf((v[2] - mu) * rs, g0.z, t0.z);
    o0.w = fmaf((v[3] - mu) * rs, g0.w, t0.w);
    o1.x = fmaf((v[4] - mu) * rs, g1.x, t1.x);
    o1.y = fmaf((v[5] - mu) * rs, g1.y, t1.y);
    o1.z = fmaf((v[6] - mu) * rs, g1.z, t1.z);
    o1.w = fmaf((v[7] - mu) * rs, g1.w, t1.w);
    *(float4*)&out[off]     = o0;
    *(float4*)&out[off + 4] = o1;
}

// ---------------------------------------------------------------------------
// Launch (strictly serial, single stream)
// ---------------------------------------------------------------------------
extern "C" void kernel_launch(void* const* d_in, const int* in_sizes, int n_in,
                              void* d_out, int out_size)
{
    const float* X       = (const float*)d_in[0];
    const float* e_add   = (const float*)d_in[1];
    const float* e_mul   = (const float*)d_in[2];
    const float* y_x_add = (const float*)d_in[3];
    const float* y_x_mul = (const float*)d_in[4];
    const float* nmask   = (const float*)d_in[5];
    const float* Wq      = (const float*)d_in[6];
    const float* bq      = (const float*)d_in[7];
    const float* Wk      = (const float*)d_in[8];
    const float* bk      = (const float*)d_in[9];
    const float* Wv      = (const float*)d_in[10];
    const float* bv      = (const float*)d_in[11];
    const float* Wo      = (const float*)d_in[12];
    const float* bo      = (const float*)d_in[13];
    const float* W1      = (const float*)d_in[14];
    const float* b1      = (const float*)d_in[15];
    const float* W2      = (const float*)d_in[16];
    const float* b2      = (const float*)d_in[17];
    const float* g1      = (const float*)d_in[18];
    const float* beta1   = (const float*)d_in[19];
    const float* g2      = (const float*)d_in[20];
    const float* beta2   = (const float*)d_in[21];
    float* out = (float*)d_out;

    float *Qb, *Kb, *Vb, *Tb, *X1b, *Hb, *Pb;
    float4* SAb;
    cudaGetSymbolAddress((void**)&Qb,  g_Q);
    cudaGetSymbolAddress((void**)&Kb,  g_K);
    cudaGetSymbolAddress((void**)&Vb,  g_V);
    cudaGetSymbolAddress((void**)&Tb,  g_T);
    cudaGetSymbolAddress((void**)&X1b, g_X1);
    cudaGetSymbolAddress((void**)&Hb,  g_H);
    cudaGetSymbolAddress((void**)&Pb,  g_P);
    cudaGetSymbolAddress((void**)&SAb, g_SA);

    // 1) QKV projections, fused along N (384 CTAs)
    {
        GArgs a = {};
        a.A = X;
        a.B[0] = Wq; a.B[1] = Wk; a.B[2] = Wv;
        a.bias[0] = bq; a.bias[1] = bk; a.bias[2] = bv;
        a.C[0] = Qb; a.C[1] = Kb; a.C[2] = Vb;
        a.M = ROWS; a.N = DX; a.lda = DX; a.kPerZ = DX; a.relu = 0; a.mode = 0;
        dim3 grid(3 * DX / BN, ROWS / BM, 1);
        sgemm_kernel<<<grid, 128>>>(a);
    }

    // 2) attention partials (2048 CTAs, R12 config) + combine
    {
        dim3 grid(ROWS / 4, JSPLIT);
        attn_part_kernel<<<grid, 256>>>(Qb, Kb, Vb, e_add, e_mul, nmask, SAb);
    }
    attn_combine_kernel<<<ROWS / 4, 256>>>(SAb, y_x_add, y_x_mul, Tb);

    // 3) Wo partials (split-K=4, 512 CTAs); bias folded into LN1
    {
        GArgs a = {};
        a.A = Tb; a.B[0] = Wo; a.C[0] = Pb;
        a.M = ROWS; a.N = DX; a.lda = DX; a.kPerZ = DX / 4; a.relu = 0; a.mode = 1;
        dim3 grid(DX / BN, ROWS / BM, 4);
        sgemm_kernel<<<grid, 128>>>(a);
    }

    // 4) X1 = LN(X + mask*(sum P + bo))   (warp-per-row, 128 CTAs)
    ln_kernel<<<ROWS / 8, 256>>>(X, Pb, 4, bo, nmask, g1, beta1, X1b);

    // 5) H = relu(X1 @ W1 + b1)  (512 CTAs)
    {
        GArgs a = {};
        a.A = X1b; a.B[0] = W1; a.bias[0] = b1; a.C[0] = Hb;
        a.M = ROWS; a.N = DFF; a.lda = DX; a.kPerZ = DX; a.relu = 1; a.mode = 0;
        dim3 grid(DFF / BN, ROWS / BM, 1);
        sgemm_kernel<<<grid, 128>>>(a);
    }

    // 6) W2 partials (split-K=4, 512 CTAs); bias folded into LN2
    {
        GArgs a = {};
        a.A = Hb; a.B[0] = W2; a.C[0] = Pb;
        a.M = ROWS; a.N = DX; a.lda = DFF; a.kPerZ = DFF / 4; a.relu = 0; a.mode = 1;
        dim3 grid(DX / BN, ROWS / BM, 4);
        sgemm_kernel<<<grid, 128>>>(a);
    }

    // 7) out = LN(X1 + sum P + b2)   (warp-per-row, 128 CTAs)
    ln_kernel<<<ROWS / 8, 256>>>(X1b, Pb, 4, b2, (const float*)nullptr,
                                 g2, beta2, out);
}